// round 5
// baseline (speedup 1.0000x reference)
#include <cuda_runtime.h>
#include <cuda_bf16.h>

#define Bn 64
#define Sn 1024
#define Vn 32000
#define Dn 1024
#define Hn 1024
#define En 1024
#define An 1024

// ---------------- scratch (no allocs allowed) ----------------
__device__ float g_q[Bn * An];
__device__ float g_score[Bn * Sn];
__device__ float g_x[Bn * (Dn + En)];
__device__ float g_gates[Bn * 4 * Hn];
__device__ float g_enc_tf[(size_t)Bn * Sn * En];  // tf32-rounded enc
__device__ float g_wae_tf[(size_t)An * En];       // tf32-rounded Wa_e

// ---------------- helpers ----------------
__device__ __forceinline__ unsigned f2tf(float f) {
    unsigned u;
    asm("cvt.rna.tf32.f32 %0, %1;" : "=r"(u) : "f"(f));
    return u;
}

__device__ __forceinline__ void mma_tf32(float* c, const unsigned* a, const unsigned* b) {
    asm volatile(
        "mma.sync.aligned.m16n8k8.row.col.f32.tf32.tf32.f32 "
        "{%0,%1,%2,%3}, {%4,%5,%6,%7}, {%8,%9}, {%0,%1,%2,%3};"
        : "+f"(c[0]), "+f"(c[1]), "+f"(c[2]), "+f"(c[3])
        : "r"(a[0]), "r"(a[1]), "r"(a[2]), "r"(a[3]), "r"(b[0]), "r"(b[1]));
}

__device__ __forceinline__ void ldsm4(unsigned* r, unsigned addr) {
    asm volatile("ldmatrix.sync.aligned.m8n8.x4.shared.b16 {%0,%1,%2,%3}, [%4];"
                 : "=r"(r[0]), "=r"(r[1]), "=r"(r[2]), "=r"(r[3]) : "r"(addr));
}

__device__ __forceinline__ void cp_async16(unsigned saddr, const void* gptr) {
    asm volatile("cp.async.ca.shared.global [%0], [%1], 16;" :: "r"(saddr), "l"(gptr));
}
__device__ __forceinline__ void cp_commit() { asm volatile("cp.async.commit_group;"); }

// ---------------- tf32 pre-convert ----------------
__global__ void tf32_convert(const float* __restrict__ src, float* __restrict__ dst) {
    size_t i = ((size_t)blockIdx.x * 256 + threadIdx.x) * 4;
    float4 v = *(const float4*)(src + i);
    uint4 o;
    o.x = f2tf(v.x); o.y = f2tf(v.y); o.z = f2tf(v.z); o.w = f2tf(v.w);
    *(uint4*)(dst + i) = o;
}

// ---------------- embedding gather ----------------
__global__ void embed_kernel(const int* __restrict__ input_step,
                             const float* __restrict__ emb,
                             float* __restrict__ xbuf) {
    int b = blockIdx.x;
    int row = input_step[b];
    const float* src = emb + (size_t)row * Dn;
    float* dst = xbuf + (size_t)b * (Dn + En);
    for (int d = threadIdx.x; d < Dn; d += blockDim.x) dst[d] = src[d];
}

// ---------------- fp32 small-M GEMM: C[64,N] = A[64,K] @ W[N,K]^T ----------------
__global__ void gemm_nt(const float* __restrict__ Amat,
                        const float* __restrict__ Wmat,
                        const float* __restrict__ bias,
                        const float* __restrict__ bias2,
                        float* __restrict__ Cmat,
                        int K, int N, int accumulate) {
    __shared__ float As[16][64];
    __shared__ float Ws[16][64];

    int tid = threadIdx.x;
    int tr = tid >> 4;
    int tc = tid & 15;
    int n0 = blockIdx.x * 64;

    int lm = tid >> 2;
    int lk = (tid & 3) * 4;

    float acc[4][4];
#pragma unroll
    for (int i = 0; i < 4; i++)
#pragma unroll
        for (int j = 0; j < 4; j++) acc[i][j] = 0.f;

    for (int k0 = 0; k0 < K; k0 += 16) {
        float4 a = *(const float4*)&Amat[(size_t)lm * K + k0 + lk];
        float4 w = *(const float4*)&Wmat[(size_t)(n0 + lm) * K + k0 + lk];
        As[lk + 0][lm] = a.x; As[lk + 1][lm] = a.y; As[lk + 2][lm] = a.z; As[lk + 3][lm] = a.w;
        Ws[lk + 0][lm] = w.x; Ws[lk + 1][lm] = w.y; Ws[lk + 2][lm] = w.z; Ws[lk + 3][lm] = w.w;
        __syncthreads();
#pragma unroll
        for (int k = 0; k < 16; k++) {
            float4 av = *(const float4*)&As[k][tr * 4];
            float4 wv = *(const float4*)&Ws[k][tc * 4];
            float ar[4] = {av.x, av.y, av.z, av.w};
            float wr[4] = {wv.x, wv.y, wv.z, wv.w};
#pragma unroll
            for (int i = 0; i < 4; i++)
#pragma unroll
                for (int j = 0; j < 4; j++) acc[i][j] += ar[i] * wr[j];
        }
        __syncthreads();
    }

#pragma unroll
    for (int i = 0; i < 4; i++) {
        int m = tr * 4 + i;
#pragma unroll
        for (int j = 0; j < 4; j++) {
            int n = n0 + tc * 4 + j;
            float v = acc[i][j];
            if (bias)  v += bias[n];
            if (bias2) v += bias2[n];
            if (accumulate) v += Cmat[(size_t)m * N + n];
            Cmat[(size_t)m * N + n] = v;
        }
    }
}

// ---------------- score init ----------------
__global__ void score_init_kernel(const float* __restrict__ bva, float* __restrict__ score) {
    int i = blockIdx.x * blockDim.x + threadIdx.x;
    if (i < Bn * Sn) score[i] = bva[0];
}

// ---------------- fused attention score GEMM ----------------
// BM=128, BN=64, BK=32. 256 threads = 8 warps (4 m-warps x 2 n-warps), warp tile 32x32.
// cp.async double buffer + ldmatrix.x4 fragments, XOR-swizzled smem.
// grid: (A/64 = 16, BS/128 = 512), x fastest -> enc tile L2 reuse.
__global__ __launch_bounds__(256) void score_gemm_mma(
        const float* __restrict__ enc_tf, const float* __restrict__ wae_tf,
        const float* __restrict__ ba_e, const float* __restrict__ q,
        const float* __restrict__ va, float* __restrict__ score) {
    extern __shared__ char smem_raw[];
    unsigned sbase = (unsigned)__cvta_generic_to_shared(smem_raw);
    const unsigned Abuf[2] = {sbase, sbase + 16384};           // 128 rows x 128B
    const unsigned Wbuf[2] = {sbase + 32768, sbase + 40960};   // 64 rows x 128B
    float* qb  = (float*)(smem_raw + 49152);
    float* vas = qb + 64;

    int tid = threadIdx.x;
    int w = tid >> 5, lane = tid & 31, g = lane >> 2, tig = lane & 3;
    int n0 = blockIdx.x * 64;
    int m0 = blockIdx.y * 128;
    int b = m0 >> 10;
    int mb = (w >> 1) * 32;
    int nb = (w & 1) * 32;

    if (tid < 64) {
        qb[tid]  = q[b * An + n0 + tid] + ba_e[n0 + tid];
        vas[tid] = va[n0 + tid];
    }

    // cp.async source/dest geometry (chunk = 16B)
    int crow = tid >> 3;        // 0..31 (+32*i)
    int ccol = tid & 7;         // 0..7
    const float* encp = enc_tf + (size_t)m0 * En;
    const float* waep = wae_tf + (size_t)n0 * En;

    // ldmatrix per-thread row bases
    int rA = mb + (lane & 15);
    int akh = (lane >> 4) & 1;                       // k half (0/1 -> +0/+4 cols)
    unsigned aRow0 = rA * 128, aRow1 = (rA + 16) * 128;
    int am = rA & 7;                                 // xor mask (same for rA+16)
    int rB = nb + ((lane >> 1) & 8) + (lane & 7);
    int bkh = (lane >> 3) & 1;
    unsigned bRow0 = rB * 128, bRow1 = (rB + 16) * 128;
    int bm = rB & 7;

    float acc[2][4][4];
#pragma unroll
    for (int mt = 0; mt < 2; mt++)
#pragma unroll
        for (int nf = 0; nf < 4; nf++)
#pragma unroll
            for (int r = 0; r < 4; r++) acc[mt][nf][r] = 0.f;

#define PREFETCH(st, k0)                                                          \
    do {                                                                          \
        _Pragma("unroll")                                                         \
        for (int i = 0; i < 4; i++) {                                             \
            int row = crow + i * 32;                                              \
            cp_async16(Abuf[st] + row * 128 + ((ccol ^ (row & 7)) << 4),          \
                       encp + (size_t)row * En + (k0) + ccol * 4);                \
        }                                                                         \
        _Pragma("unroll")                                                         \
        for (int i = 0; i < 2; i++) {                                             \
            int row = crow + i * 32;                                              \
            cp_async16(Wbuf[st] + row * 128 + ((ccol ^ (row & 7)) << 4),          \
                       waep + (size_t)row * En + (k0) + ccol * 4);                \
        }                                                                         \
        cp_commit();                                                              \
    } while (0)

    PREFETCH(0, 0);

    const int NT = En / 32;  // 32 k-tiles
    for (int it = 0; it < NT; it++) {
        if (it + 1 < NT) {
            PREFETCH((it + 1) & 1, (it + 1) * 32);
            asm volatile("cp.async.wait_group 1;");
        } else {
            asm volatile("cp.async.wait_group 0;");
        }
        __syncthreads();

        unsigned Ab = Abuf[it & 1], Wb = Wbuf[it & 1];
#pragma unroll
        for (int ks = 0; ks < 4; ks++) {
            unsigned a0[4], a1[4], b0[4], b1[4];
            unsigned acol = ((unsigned)(ks * 2 + akh) ^ am) << 4;
            unsigned bcol = ((unsigned)(ks * 2 + bkh) ^ bm) << 4;
            ldsm4(a0, Ab + aRow0 + acol);
            ldsm4(a1, Ab + aRow1 + acol);
            ldsm4(b0, Wb + bRow0 + bcol);
            ldsm4(b1, Wb + bRow1 + bcol);
            mma_tf32(acc[0][0], a0, b0);
            mma_tf32(acc[0][1], a0, b0 + 2);
            mma_tf32(acc[1][0], a1, b0);
            mma_tf32(acc[1][1], a1, b0 + 2);
            mma_tf32(acc[0][2], a0, b1);
            mma_tf32(acc[0][3], a0, b1 + 2);
            mma_tf32(acc[1][2], a1, b1);
            mma_tf32(acc[1][3], a1, b1 + 2);
        }
        __syncthreads();
    }
#undef PREFETCH

    // epilogue: tanh + va-weighted row reduction
#pragma unroll
    for (int mt = 0; mt < 2; mt++) {
        float sumlo = 0.f, sumhi = 0.f;
#pragma unroll
        for (int nf = 0; nf < 4; nf++) {
            int nl = nb + nf * 8 + 2 * tig;
            float q0 = qb[nl], q1 = qb[nl + 1];
            float v0 = vas[nl], v1 = vas[nl + 1];
            sumlo += v0 * tanhf(acc[mt][nf][0] + q0) + v1 * tanhf(acc[mt][nf][1] + q1);
            sumhi += v0 * tanhf(acc[mt][nf][2] + q0) + v1 * tanhf(acc[mt][nf][3] + q1);
        }
        sumlo += __shfl_xor_sync(0xffffffffu, sumlo, 1);
        sumlo += __shfl_xor_sync(0xffffffffu, sumlo, 2);
        sumhi += __shfl_xor_sync(0xffffffffu, sumhi, 1);
        sumhi += __shfl_xor_sync(0xffffffffu, sumhi, 2);
        if (tig == 0) {
            int r = m0 + mb + mt * 16 + g;
            atomicAdd(&score[r], sumlo);
            atomicAdd(&score[r + 8], sumhi);
        }
    }
}

// ---------------- softmax ----------------
__global__ void softmax_kernel(const float* __restrict__ score, float* __restrict__ attn) {
    __shared__ float sh[Sn];
    __shared__ float red[256];
    int b = blockIdx.x;
    int tid = threadIdx.x;

    float lmax = -3.4e38f;
    for (int s = tid; s < Sn; s += 256) {
        float v = score[b * Sn + s];
        sh[s] = v;
        lmax = fmaxf(lmax, v);
    }
    red[tid] = lmax;
    __syncthreads();
    for (int off = 128; off > 0; off >>= 1) {
        if (tid < off) red[tid] = fmaxf(red[tid], red[tid + off]);
        __syncthreads();
    }
    float m = red[0];
    __syncthreads();

    float lsum = 0.f;
    for (int s = tid; s < Sn; s += 256) {
        float e = expf(sh[s] - m);
        sh[s] = e;
        lsum += e;
    }
    red[tid] = lsum;
    __syncthreads();
    for (int off = 128; off > 0; off >>= 1) {
        if (tid < off) red[tid] += red[tid + off];
        __syncthreads();
    }
    float inv = 1.f / red[0];
    __syncthreads();

    for (int s = tid; s < Sn; s += 256) attn[b * Sn + s] = sh[s] * inv;
}

// ---------------- context = attn @ enc ----------------
__global__ void context_kernel(const float* __restrict__ enc,
                               const float* __restrict__ attn,
                               float* __restrict__ xbuf) {
    __shared__ float w[Sn];
    int b = blockIdx.x;
    int e = blockIdx.y * 256 + threadIdx.x;
    for (int s = threadIdx.x; s < Sn; s += 256) w[s] = attn[b * Sn + s];
    __syncthreads();
    const float* ep = enc + (size_t)b * Sn * En + e;
    float acc = 0.f;
#pragma unroll 8
    for (int s = 0; s < Sn; s++) acc += w[s] * ep[(size_t)s * En];
    xbuf[(size_t)b * (Dn + En) + Dn + e] = acc;
}

// ---------------- LSTM pointwise ----------------
__global__ void lstm_pointwise(const float* __restrict__ gates,
                               const float* __restrict__ cprev,
                               float* __restrict__ hout,
                               float* __restrict__ cout) {
    int idx = blockIdx.x * 256 + threadIdx.x;
    if (idx >= Bn * Hn) return;
    int b = idx >> 10;
    int h = idx & 1023;
    const float* g = gates + (size_t)b * 4 * Hn;
    float ig = 1.f / (1.f + expf(-g[h]));
    float fg = 1.f / (1.f + expf(-g[Hn + h]));
    float gg = tanhf(g[2 * Hn + h]);
    float og = 1.f / (1.f + expf(-g[3 * Hn + h]));
    float c = fg * cprev[idx] + ig * gg;
    hout[idx] = og * tanhf(c);
    cout[idx] = c;
}

// ---------------- launcher ----------------
extern "C" void kernel_launch(void* const* d_in, const int* in_sizes, int n_in,
                              void* d_out, int out_size) {
    const int*   input_step = (const int*)d_in[0];
    const float* h0    = (const float*)d_in[1];
    const float* c0    = (const float*)d_in[2];
    const float* enc   = (const float*)d_in[3];
    const float* emb   = (const float*)d_in[4];
    const float* Wa_h  = (const float*)d_in[5];
    const float* ba_h  = (const float*)d_in[6];
    const float* Wa_e  = (const float*)d_in[7];
    const float* ba_e  = (const float*)d_in[8];
    const float* va    = (const float*)d_in[9];
    const float* bva   = (const float*)d_in[10];
    const float* Wih0  = (const float*)d_in[11];
    const float* Whh0  = (const float*)d_in[12];
    const float* bih0  = (const float*)d_in[13];
    const float* bhh0  = (const float*)d_in[14];
    const float* Wih1  = (const float*)d_in[15];
    const float* Whh1  = (const float*)d_in[16];
    const float* bih1  = (const float*)d_in[17];
    const float* bhh1  = (const float*)d_in[18];
    const float* Wout  = (const float*)d_in[19];
    const float* bout  = (const float*)d_in[20];

    float* out = (float*)d_out;
    float* out_logits = out;
    float* out_h      = out_logits + Bn * Vn;
    float* out_c      = out_h + 2 * Bn * Hn;
    float* out_attn   = out_c + 2 * Bn * Hn;

    float* q_buf;     cudaGetSymbolAddress((void**)&q_buf, g_q);
    float* score_buf; cudaGetSymbolAddress((void**)&score_buf, g_score);
    float* x_buf;     cudaGetSymbolAddress((void**)&x_buf, g_x);
    float* gates_buf; cudaGetSymbolAddress((void**)&gates_buf, g_gates);
    float* enc_tf;    cudaGetSymbolAddress((void**)&enc_tf, g_enc_tf);
    float* wae_tf;    cudaGetSymbolAddress((void**)&wae_tf, g_wae_tf);

    const int score_smem = 49152 + 512;
    cudaFuncSetAttribute(score_gemm_mma, cudaFuncAttributeMaxDynamicSharedMemorySize,
                         score_smem);

    // 0. pre-round enc and Wa_e to tf32 (rna)
    tf32_convert<<<(Bn * Sn * En) / 1024, 256>>>(enc, enc_tf);
    tf32_convert<<<(An * En) / 1024, 256>>>(Wa_e, wae_tf);

    // 1. embedding gather
    embed_kernel<<<Bn, 256>>>(input_step, emb, x_buf);

    // 2. q = h0[1] @ Wa_h^T + ba_h
    gemm_nt<<<An / 64, 256>>>(h0 + Bn * Hn, Wa_h, ba_h, nullptr, q_buf, Hn, An, 0);

    // 3. fused tf32 score GEMM
    score_init_kernel<<<(Bn * Sn + 255) / 256, 256>>>(bva, score_buf);
    {
        dim3 grid(An / 64, Bn * Sn / 128);
        score_gemm_mma<<<grid, 256, score_smem>>>(enc_tf, wae_tf, ba_e, q_buf, va, score_buf);
    }

    // 4. softmax
    softmax_kernel<<<Bn, 256>>>(score_buf, out_attn);

    // 5. context
    {
        dim3 grid(Bn, En / 256);
        context_kernel<<<grid, 256>>>(enc, out_attn, x_buf);
    }

    // 6. LSTM layer 0
    gemm_nt<<<4 * Hn / 64, 256>>>(x_buf, Wih0, bih0, bhh0, gates_buf, Dn + En, 4 * Hn, 0);
    gemm_nt<<<4 * Hn / 64, 256>>>(h0, Whh0, nullptr, nullptr, gates_buf, Hn, 4 * Hn, 1);
    lstm_pointwise<<<(Bn * Hn + 255) / 256, 256>>>(gates_buf, c0, out_h, out_c);

    // 7. LSTM layer 1
    gemm_nt<<<4 * Hn / 64, 256>>>(out_h, Wih1, bih1, bhh1, gates_buf, Hn, 4 * Hn, 0);
    gemm_nt<<<4 * Hn / 64, 256>>>(h0 + Bn * Hn, Whh1, nullptr, nullptr, gates_buf, Hn, 4 * Hn, 1);
    lstm_pointwise<<<(Bn * Hn + 255) / 256, 256>>>(gates_buf, c0 + Bn * Hn,
                                                   out_h + Bn * Hn, out_c + Bn * Hn);

    // 8. logits
    gemm_nt<<<Vn / 64, 256>>>(out_h + Bn * Hn, Wout, bout, nullptr, out_logits, Hn, Vn, 0);
}

// round 6
// speedup vs baseline: 1.2620x; 1.2620x over previous
#include <cuda_runtime.h>
#include <cuda_bf16.h>

#define Bn 64
#define Sn 1024
#define Vn 32000
#define Dn 1024
#define Hn 1024
#define En 1024
#define An 1024

// ---------------- scratch (no allocs allowed) ----------------
__device__ float g_q[Bn * An];
__device__ float g_score[Bn * Sn];
__device__ float g_x[Bn * (Dn + En)];
__device__ float g_gates[Bn * 4 * Hn];
__device__ float g_enc_tf[(size_t)Bn * Sn * En];  // tf32-rounded enc
__device__ float g_wae_tf[(size_t)An * En];       // tf32-rounded Wa_e

// ---------------- helpers ----------------
__device__ __forceinline__ unsigned f2tf(float f) {
    unsigned u;
    asm("cvt.rna.tf32.f32 %0, %1;" : "=r"(u) : "f"(f));
    return u;
}

__device__ __forceinline__ uint4 cvt4(float4 v) {
    uint4 o;
    o.x = f2tf(v.x); o.y = f2tf(v.y); o.z = f2tf(v.z); o.w = f2tf(v.w);
    return o;
}

__device__ __forceinline__ void mma_tf32(float* c, const unsigned* a, const unsigned* b) {
    asm volatile(
        "mma.sync.aligned.m16n8k8.row.col.f32.tf32.tf32.f32 "
        "{%0,%1,%2,%3}, {%4,%5,%6,%7}, {%8,%9}, {%0,%1,%2,%3};"
        : "+f"(c[0]), "+f"(c[1]), "+f"(c[2]), "+f"(c[3])
        : "r"(a[0]), "r"(a[1]), "r"(a[2]), "r"(a[3]), "r"(b[0]), "r"(b[1]));
}

__device__ __forceinline__ void ldsm4(unsigned* r, unsigned addr) {
    asm volatile("ldmatrix.sync.aligned.m8n8.x4.shared.b16 {%0,%1,%2,%3}, [%4];"
                 : "=r"(r[0]), "=r"(r[1]), "=r"(r[2]), "=r"(r[3]) : "r"(addr));
}

__device__ __forceinline__ void cp_async16(unsigned saddr, const void* gptr) {
    asm volatile("cp.async.ca.shared.global [%0], [%1], 16;" :: "r"(saddr), "l"(gptr));
}
__device__ __forceinline__ void cp_commit() { asm volatile("cp.async.commit_group;"); }

// ---------------- tf32 pre-convert ----------------
__global__ void tf32_convert(const float* __restrict__ src, float* __restrict__ dst) {
    size_t i = ((size_t)blockIdx.x * 256 + threadIdx.x) * 4;
    float4 v = *(const float4*)(src + i);
    *(uint4*)(dst + i) = cvt4(v);
}

// ---------------- embedding gather ----------------
__global__ void embed_kernel(const int* __restrict__ input_step,
                             const float* __restrict__ emb,
                             float* __restrict__ xbuf) {
    int b = blockIdx.x;
    int row = input_step[b];
    const float* src = emb + (size_t)row * Dn;
    float* dst = xbuf + (size_t)b * (Dn + En);
    for (int d = threadIdx.x; d < Dn; d += blockDim.x) dst[d] = src[d];
}

// ---------------- tf32 TC GEMM: C[64,N] = A[64,K] @ W[N,K]^T (+bias+bias2) ----------------
// BM=64, BN=64, BK=32, 128 threads = 4 warps (2 m x 2 n), warp tile 32x32.
// In-kernel cvt.rna, reg-prefetch double buffered smem.
__global__ __launch_bounds__(128) void gemm_nt_tc(
        const float* __restrict__ Amat, const float* __restrict__ Wmat,
        const float* __restrict__ bias, const float* __restrict__ bias2,
        float* __restrict__ Cmat, int K, int N, int accumulate) {
    __shared__ char gsm[2][16384];  // per stage: A 8KB + W 8KB
    unsigned sbase = (unsigned)__cvta_generic_to_shared(gsm);

    int tid = threadIdx.x;
    int w = tid >> 5, lane = tid & 31, g = lane >> 2, tig = lane & 3;
    int n0 = blockIdx.x * 64;
    int mb = (w & 1) * 32;
    int nb = (w >> 1) * 32;

    int lr = tid >> 3;       // 0..15
    int lc16 = tid & 7;      // 16B column

    // ldmatrix per-thread geometry (validated fragment mapping)
    int rA = mb + (lane & 15);
    int akh = (lane >> 4) & 1;
    unsigned aRow0 = rA * 128, aRow1 = (rA + 16) * 128;
    int am = rA & 7;
    int rB = nb + ((lane >> 1) & 8) + (lane & 7);
    int bkh = (lane >> 3) & 1;
    unsigned bRow0 = rB * 128, bRow1 = (rB + 16) * 128;
    int bm = rB & 7;

    float acc[2][4][4];
#pragma unroll
    for (int mt = 0; mt < 2; mt++)
#pragma unroll
        for (int nf = 0; nf < 4; nf++)
#pragma unroll
            for (int r = 0; r < 4; r++) acc[mt][nf][r] = 0.f;

    float4 aReg[4], wReg[4];
#pragma unroll
    for (int i = 0; i < 4; i++) {
        int row = lr + 16 * i;
        aReg[i] = *(const float4*)&Amat[(size_t)row * K + lc16 * 4];
        wReg[i] = *(const float4*)&Wmat[(size_t)(n0 + row) * K + lc16 * 4];
    }

    int st = 0;
    for (int k0 = 0; k0 < K; k0 += 32) {
        // store staged regs (tf32-rounded, swizzled)
#pragma unroll
        for (int i = 0; i < 4; i++) {
            int row = lr + 16 * i;
            unsigned off = row * 128 + (unsigned)((lc16 ^ (row & 7)) << 4);
            *(uint4*)(gsm[st] + off) = cvt4(aReg[i]);
            *(uint4*)(gsm[st] + 8192 + off) = cvt4(wReg[i]);
        }
        __syncthreads();

        // prefetch next k-tile into regs (overlaps with MMA below)
        if (k0 + 32 < K) {
#pragma unroll
            for (int i = 0; i < 4; i++) {
                int row = lr + 16 * i;
                aReg[i] = *(const float4*)&Amat[(size_t)row * K + k0 + 32 + lc16 * 4];
                wReg[i] = *(const float4*)&Wmat[(size_t)(n0 + row) * K + k0 + 32 + lc16 * 4];
            }
        }

        unsigned Ab = sbase + st * 16384;
        unsigned Wb = Ab + 8192;
#pragma unroll
        for (int ks = 0; ks < 4; ks++) {
            unsigned a0[4], a1[4], b0[4], b1[4];
            unsigned acol = ((unsigned)(ks * 2 + akh) ^ am) << 4;
            unsigned bcol = ((unsigned)(ks * 2 + bkh) ^ bm) << 4;
            ldsm4(a0, Ab + aRow0 + acol);
            ldsm4(a1, Ab + aRow1 + acol);
            ldsm4(b0, Wb + bRow0 + bcol);
            ldsm4(b1, Wb + bRow1 + bcol);
            mma_tf32(acc[0][0], a0, b0);
            mma_tf32(acc[0][1], a0, b0 + 2);
            mma_tf32(acc[1][0], a1, b0);
            mma_tf32(acc[1][1], a1, b0 + 2);
            mma_tf32(acc[0][2], a0, b1);
            mma_tf32(acc[0][3], a0, b1 + 2);
            mma_tf32(acc[1][2], a1, b1);
            mma_tf32(acc[1][3], a1, b1 + 2);
        }
        __syncthreads();
        st ^= 1;
    }

    // epilogue
#pragma unroll
    for (int mt = 0; mt < 2; mt++) {
        int m0i = mb + mt * 16 + g;
        int m1i = m0i + 8;
#pragma unroll
        for (int nf = 0; nf < 4; nf++) {
            int n = n0 + nb + nf * 8 + 2 * tig;
            float badd0 = 0.f, badd1 = 0.f;
            if (bias)  { badd0 += bias[n];  badd1 += bias[n + 1]; }
            if (bias2) { badd0 += bias2[n]; badd1 += bias2[n + 1]; }
            float v00 = acc[mt][nf][0] + badd0, v01 = acc[mt][nf][1] + badd1;
            float v10 = acc[mt][nf][2] + badd0, v11 = acc[mt][nf][3] + badd1;
            if (accumulate) {
                v00 += Cmat[(size_t)m0i * N + n];  v01 += Cmat[(size_t)m0i * N + n + 1];
                v10 += Cmat[(size_t)m1i * N + n];  v11 += Cmat[(size_t)m1i * N + n + 1];
            }
            Cmat[(size_t)m0i * N + n] = v00;  Cmat[(size_t)m0i * N + n + 1] = v01;
            Cmat[(size_t)m1i * N + n] = v10;  Cmat[(size_t)m1i * N + n + 1] = v11;
        }
    }
}

// ---------------- score init ----------------
__global__ void score_init_kernel(const float* __restrict__ bva, float* __restrict__ score) {
    int i = blockIdx.x * blockDim.x + threadIdx.x;
    if (i < Bn * Sn) score[i] = bva[0];
}

// ---------------- fused attention score GEMM ----------------
// BM=128, BN=64, BK=32, 256 threads (8 warps: 4m x 2n, warp tile 32x32).
// 3-stage cp.async pipeline, single syncthreads per iter.
__global__ __launch_bounds__(256) void score_gemm_mma(
        const float* __restrict__ enc_tf, const float* __restrict__ wae_tf,
        const float* __restrict__ ba_e, const float* __restrict__ q,
        const float* __restrict__ va, float* __restrict__ score) {
    extern __shared__ char smem_raw[];
    unsigned sbase = (unsigned)__cvta_generic_to_shared(smem_raw);
    const unsigned STAGE = 24576;  // A 16KB + W 8KB
    float* qb  = (float*)(smem_raw + 3 * STAGE);
    float* vas = qb + 64;

    int tid = threadIdx.x;
    int w = tid >> 5, lane = tid & 31, g = lane >> 2, tig = lane & 3;
    int n0 = blockIdx.x * 64;
    int m0 = blockIdx.y * 128;
    int b = m0 >> 10;
    int mb = (w >> 1) * 32;
    int nb = (w & 1) * 32;

    if (tid < 64) {
        qb[tid]  = q[b * An + n0 + tid] + ba_e[n0 + tid];
        vas[tid] = va[n0 + tid];
    }

    int crow = tid >> 3;
    int ccol = tid & 7;
    const float* encp = enc_tf + (size_t)m0 * En;
    const float* waep = wae_tf + (size_t)n0 * En;

    int rA = mb + (lane & 15);
    int akh = (lane >> 4) & 1;
    unsigned aRow0 = rA * 128, aRow1 = (rA + 16) * 128;
    int am = rA & 7;
    int rB = nb + ((lane >> 1) & 8) + (lane & 7);
    int bkh = (lane >> 3) & 1;
    unsigned bRow0 = rB * 128, bRow1 = (rB + 16) * 128;
    int bm = rB & 7;

    float acc[2][4][4];
#pragma unroll
    for (int mt = 0; mt < 2; mt++)
#pragma unroll
        for (int nf = 0; nf < 4; nf++)
#pragma unroll
            for (int r = 0; r < 4; r++) acc[mt][nf][r] = 0.f;

#define PREFETCH(st, k0)                                                          \
    do {                                                                          \
        unsigned Ad = sbase + (st) * STAGE;                                       \
        unsigned Wd = Ad + 16384;                                                 \
        _Pragma("unroll")                                                         \
        for (int i = 0; i < 4; i++) {                                             \
            int row = crow + i * 32;                                              \
            cp_async16(Ad + row * 128 + ((ccol ^ (row & 7)) << 4),                \
                       encp + (size_t)row * En + (k0) + ccol * 4);                \
        }                                                                         \
        _Pragma("unroll")                                                         \
        for (int i = 0; i < 2; i++) {                                             \
            int row = crow + i * 32;                                              \
            cp_async16(Wd + row * 128 + ((ccol ^ (row & 7)) << 4),                \
                       waep + (size_t)row * En + (k0) + ccol * 4);                \
        }                                                                         \
        cp_commit();                                                              \
    } while (0)

    PREFETCH(0, 0);
    PREFETCH(1, 32);

    const int NT = En / 32;
    int st = 0;
    for (int it = 0; it < NT; it++) {
        if (it == NT - 1) asm volatile("cp.async.wait_group 0;");
        else              asm volatile("cp.async.wait_group 1;");
        __syncthreads();

        unsigned Ab = sbase + st * STAGE;
        unsigned Wb = Ab + 16384;
#pragma unroll
        for (int ks = 0; ks < 4; ks++) {
            unsigned a0[4], a1[4], b0[4], b1[4];
            unsigned acol = ((unsigned)(ks * 2 + akh) ^ am) << 4;
            unsigned bcol = ((unsigned)(ks * 2 + bkh) ^ bm) << 4;
            ldsm4(a0, Ab + aRow0 + acol);
            ldsm4(a1, Ab + aRow1 + acol);
            ldsm4(b0, Wb + bRow0 + bcol);
            ldsm4(b1, Wb + bRow1 + bcol);
            mma_tf32(acc[0][0], a0, b0);
            mma_tf32(acc[0][1], a0, b0 + 2);
            mma_tf32(acc[1][0], a1, b0);
            mma_tf32(acc[1][1], a1, b0 + 2);
            mma_tf32(acc[0][2], a0, b1);
            mma_tf32(acc[0][3], a0, b1 + 2);
            mma_tf32(acc[1][2], a1, b1);
            mma_tf32(acc[1][3], a1, b1 + 2);
        }

        int pf = it + 2;
        if (pf < NT) {
            int pst = pf % 3 == 0 ? 0 : (pf % 3);  // pf%3
            PREFETCH(pf % 3, pf * 32);
            (void)pst;
        }
        st = (st + 1 == 3) ? 0 : st + 1;
    }
#undef PREFETCH

    // epilogue: tanh + va-weighted row reduction
#pragma unroll
    for (int mt = 0; mt < 2; mt++) {
        float sumlo = 0.f, sumhi = 0.f;
#pragma unroll
        for (int nf = 0; nf < 4; nf++) {
            int nl = nb + nf * 8 + 2 * tig;
            float q0 = qb[nl], q1 = qb[nl + 1];
            float v0 = vas[nl], v1 = vas[nl + 1];
            sumlo += v0 * tanhf(acc[mt][nf][0] + q0) + v1 * tanhf(acc[mt][nf][1] + q1);
            sumhi += v0 * tanhf(acc[mt][nf][2] + q0) + v1 * tanhf(acc[mt][nf][3] + q1);
        }
        sumlo += __shfl_xor_sync(0xffffffffu, sumlo, 1);
        sumlo += __shfl_xor_sync(0xffffffffu, sumlo, 2);
        sumhi += __shfl_xor_sync(0xffffffffu, sumhi, 1);
        sumhi += __shfl_xor_sync(0xffffffffu, sumhi, 2);
        if (tig == 0) {
            int r = m0 + mb + mt * 16 + g;
            atomicAdd(&score[r], sumlo);
            atomicAdd(&score[r + 8], sumhi);
        }
    }
}

// ---------------- softmax ----------------
__global__ void softmax_kernel(const float* __restrict__ score, float* __restrict__ attn) {
    __shared__ float sh[Sn];
    __shared__ float red[256];
    int b = blockIdx.x;
    int tid = threadIdx.x;

    float lmax = -3.4e38f;
    for (int s = tid; s < Sn; s += 256) {
        float v = score[b * Sn + s];
        sh[s] = v;
        lmax = fmaxf(lmax, v);
    }
    red[tid] = lmax;
    __syncthreads();
    for (int off = 128; off > 0; off >>= 1) {
        if (tid < off) red[tid] = fmaxf(red[tid], red[tid + off]);
        __syncthreads();
    }
    float m = red[0];
    __syncthreads();

    float lsum = 0.f;
    for (int s = tid; s < Sn; s += 256) {
        float e = expf(sh[s] - m);
        sh[s] = e;
        lsum += e;
    }
    red[tid] = lsum;
    __syncthreads();
    for (int off = 128; off > 0; off >>= 1) {
        if (tid < off) red[tid] += red[tid + off];
        __syncthreads();
    }
    float inv = 1.f / red[0];
    __syncthreads();

    for (int s = tid; s < Sn; s += 256) attn[b * Sn + s] = sh[s] * inv;
}

// ---------------- context = attn @ enc ----------------
__global__ void context_kernel(const float* __restrict__ enc,
                               const float* __restrict__ attn,
                               float* __restrict__ xbuf) {
    __shared__ float w[Sn];
    int b = blockIdx.x;
    int e = blockIdx.y * 256 + threadIdx.x;
    for (int s = threadIdx.x; s < Sn; s += 256) w[s] = attn[b * Sn + s];
    __syncthreads();
    const float* ep = enc + (size_t)b * Sn * En + e;
    float acc = 0.f;
#pragma unroll 8
    for (int s = 0; s < Sn; s++) acc += w[s] * ep[(size_t)s * En];
    xbuf[(size_t)b * (Dn + En) + Dn + e] = acc;
}

// ---------------- LSTM pointwise ----------------
__global__ void lstm_pointwise(const float* __restrict__ gates,
                               const float* __restrict__ cprev,
                               float* __restrict__ hout,
                               float* __restrict__ cout) {
    int idx = blockIdx.x * 256 + threadIdx.x;
    if (idx >= Bn * Hn) return;
    int b = idx >> 10;
    int h = idx & 1023;
    const float* g = gates + (size_t)b * 4 * Hn;
    float ig = 1.f / (1.f + expf(-g[h]));
    float fg = 1.f / (1.f + expf(-g[Hn + h]));
    float gg = tanhf(g[2 * Hn + h]);
    float og = 1.f / (1.f + expf(-g[3 * Hn + h]));
    float c = fg * cprev[idx] + ig * gg;
    hout[idx] = og * tanhf(c);
    cout[idx] = c;
}

// ---------------- launcher ----------------
extern "C" void kernel_launch(void* const* d_in, const int* in_sizes, int n_in,
                              void* d_out, int out_size) {
    const int*   input_step = (const int*)d_in[0];
    const float* h0    = (const float*)d_in[1];
    const float* c0    = (const float*)d_in[2];
    const float* enc   = (const float*)d_in[3];
    const float* emb   = (const float*)d_in[4];
    const float* Wa_h  = (const float*)d_in[5];
    const float* ba_h  = (const float*)d_in[6];
    const float* Wa_e  = (const float*)d_in[7];
    const float* ba_e  = (const float*)d_in[8];
    const float* va    = (const float*)d_in[9];
    const float* bva   = (const float*)d_in[10];
    const float* Wih0  = (const float*)d_in[11];
    const float* Whh0  = (const float*)d_in[12];
    const float* bih0  = (const float*)d_in[13];
    const float* bhh0  = (const float*)d_in[14];
    const float* Wih1  = (const float*)d_in[15];
    const float* Whh1  = (const float*)d_in[16];
    const float* bih1  = (const float*)d_in[17];
    const float* bhh1  = (const float*)d_in[18];
    const float* Wout  = (const float*)d_in[19];
    const float* bout  = (const float*)d_in[20];

    float* out = (float*)d_out;
    float* out_logits = out;
    float* out_h      = out_logits + Bn * Vn;
    float* out_c      = out_h + 2 * Bn * Hn;
    float* out_attn   = out_c + 2 * Bn * Hn;

    float* q_buf;     cudaGetSymbolAddress((void**)&q_buf, g_q);
    float* score_buf; cudaGetSymbolAddress((void**)&score_buf, g_score);
    float* x_buf;     cudaGetSymbolAddress((void**)&x_buf, g_x);
    float* gates_buf; cudaGetSymbolAddress((void**)&gates_buf, g_gates);
    float* enc_tf;    cudaGetSymbolAddress((void**)&enc_tf, g_enc_tf);
    float* wae_tf;    cudaGetSymbolAddress((void**)&wae_tf, g_wae_tf);

    const int score_smem = 3 * 24576 + 512;  // 74240
    cudaFuncSetAttribute(score_gemm_mma, cudaFuncAttributeMaxDynamicSharedMemorySize,
                         score_smem);

    // 0. pre-round enc and Wa_e to tf32 (rna)
    tf32_convert<<<(Bn * Sn * En) / 1024, 256>>>(enc, enc_tf);
    tf32_convert<<<(An * En) / 1024, 256>>>(Wa_e, wae_tf);

    // 1. embedding gather
    embed_kernel<<<Bn, 256>>>(input_step, emb, x_buf);

    // 2. q = h0[1] @ Wa_h^T + ba_h
    gemm_nt_tc<<<An / 64, 128>>>(h0 + Bn * Hn, Wa_h, ba_h, nullptr, q_buf, Hn, An, 0);

    // 3. fused tf32 score GEMM
    score_init_kernel<<<(Bn * Sn + 255) / 256, 256>>>(bva, score_buf);
    {
        dim3 grid(An / 64, Bn * Sn / 128);
        score_gemm_mma<<<grid, 256, score_smem>>>(enc_tf, wae_tf, ba_e, q_buf, va, score_buf);
    }

    // 4. softmax
    softmax_kernel<<<Bn, 256>>>(score_buf, out_attn);

    // 5. context
    {
        dim3 grid(Bn, En / 256);
        context_kernel<<<grid, 256>>>(enc, out_attn, x_buf);
    }

    // 6. LSTM layer 0
    gemm_nt_tc<<<4 * Hn / 64, 128>>>(x_buf, Wih0, bih0, bhh0, gates_buf, Dn + En, 4 * Hn, 0);
    gemm_nt_tc<<<4 * Hn / 64, 128>>>(h0, Whh0, nullptr, nullptr, gates_buf, Hn, 4 * Hn, 1);
    lstm_pointwise<<<(Bn * Hn + 255) / 256, 256>>>(gates_buf, c0, out_h, out_c);

    // 7. LSTM layer 1
    gemm_nt_tc<<<4 * Hn / 64, 128>>>(out_h, Wih1, bih1, bhh1, gates_buf, Hn, 4 * Hn, 0);
    gemm_nt_tc<<<4 * Hn / 64, 128>>>(h0 + Bn * Hn, Whh1, nullptr, nullptr, gates_buf, Hn, 4 * Hn, 1);
    lstm_pointwise<<<(Bn * Hn + 255) / 256, 256>>>(gates_buf, c0 + Bn * Hn,
                                                   out_h + Bn * Hn, out_c + Bn * Hn);

    // 8. logits
    gemm_nt_tc<<<Vn / 64, 128>>>(out_h + Bn * Hn, Wout, bout, nullptr, out_logits, Hn, Vn, 0);
}

// round 7
// speedup vs baseline: 1.3868x; 1.0988x over previous
#include <cuda_runtime.h>
#include <cuda_bf16.h>

#define Bn 64
#define Sn 1024
#define Vn 32000
#define Dn 1024
#define Hn 1024
#define En 1024
#define An 1024

// ---------------- scratch (no allocs allowed) ----------------
__device__ float g_q[Bn * An];
__device__ float g_score[Bn * Sn];
__device__ float g_x[Bn * (Dn + En)];
__device__ float g_gates[Bn * 4 * Hn];
__device__ float g_enc_tf[(size_t)Bn * Sn * En];  // tf32-rounded enc
__device__ float g_wae_tf[(size_t)An * En];       // tf32-rounded Wa_e

// ---------------- helpers ----------------
__device__ __forceinline__ unsigned f2tf(float f) {
    unsigned u;
    asm("cvt.rna.tf32.f32 %0, %1;" : "=r"(u) : "f"(f));
    return u;
}

__device__ __forceinline__ uint4 cvt4(float4 v) {
    uint4 o;
    o.x = f2tf(v.x); o.y = f2tf(v.y); o.z = f2tf(v.z); o.w = f2tf(v.w);
    return o;
}

__device__ __forceinline__ void mma_tf32(float* c, const unsigned* a, const unsigned* b) {
    asm volatile(
        "mma.sync.aligned.m16n8k8.row.col.f32.tf32.tf32.f32 "
        "{%0,%1,%2,%3}, {%4,%5,%6,%7}, {%8,%9}, {%0,%1,%2,%3};"
        : "+f"(c[0]), "+f"(c[1]), "+f"(c[2]), "+f"(c[3])
        : "r"(a[0]), "r"(a[1]), "r"(a[2]), "r"(a[3]), "r"(b[0]), "r"(b[1]));
}

__device__ __forceinline__ void ldsm4(unsigned* r, unsigned addr) {
    asm volatile("ldmatrix.sync.aligned.m8n8.x4.shared.b16 {%0,%1,%2,%3}, [%4];"
                 : "=r"(r[0]), "=r"(r[1]), "=r"(r[2]), "=r"(r[3]) : "r"(addr));
}

__device__ __forceinline__ void cp_async16(unsigned saddr, const void* gptr) {
    asm volatile("cp.async.ca.shared.global [%0], [%1], 16;" :: "r"(saddr), "l"(gptr));
}
__device__ __forceinline__ void cp_commit() { asm volatile("cp.async.commit_group;"); }

// ---------------- tf32 pre-convert ----------------
__global__ void tf32_convert(const float* __restrict__ src, float* __restrict__ dst) {
    size_t i = ((size_t)blockIdx.x * 256 + threadIdx.x) * 4;
    float4 v = *(const float4*)(src + i);
    *(uint4*)(dst + i) = cvt4(v);
}

// ---------------- embedding gather ----------------
__global__ void embed_kernel(const int* __restrict__ input_step,
                             const float* __restrict__ emb,
                             float* __restrict__ xbuf) {
    int b = blockIdx.x;
    int row = input_step[b];
    const float* src = emb + (size_t)row * Dn;
    float* dst = xbuf + (size_t)b * (Dn + En);
    for (int d = threadIdx.x; d < Dn; d += blockDim.x) dst[d] = src[d];
}

// ---------------- tf32 TC GEMM: C[64,N] = A[64,K] @ W[N,K]^T (+bias+bias2) ----------------
// BM=64, BN=64, BK=32, 128 threads = 4 warps (2 m x 2 n), warp tile 32x32.
__global__ __launch_bounds__(128) void gemm_nt_tc(
        const float* __restrict__ Amat, const float* __restrict__ Wmat,
        const float* __restrict__ bias, const float* __restrict__ bias2,
        float* __restrict__ Cmat, int K, int N, int accumulate) {
    __shared__ char gsm[2][16384];  // per stage: A 8KB + W 8KB
    unsigned sbase = (unsigned)__cvta_generic_to_shared(gsm);

    int tid = threadIdx.x;
    int w = tid >> 5, lane = tid & 31, g = lane >> 2, tig = lane & 3;
    int n0 = blockIdx.x * 64;
    int mb = (w & 1) * 32;
    int nb = (w >> 1) * 32;

    int lr = tid >> 3;       // 0..15
    int lc16 = tid & 7;      // 16B column

    int rA = mb + (lane & 15);
    int akh = (lane >> 4) & 1;
    unsigned aRow0 = rA * 128, aRow1 = (rA + 16) * 128;
    int am = rA & 7;
    int rB = nb + ((lane >> 1) & 8) + (lane & 7);
    int bkh = (lane >> 3) & 1;
    unsigned bRow0 = rB * 128, bRow1 = (rB + 16) * 128;
    int bm = rB & 7;

    float acc[2][4][4];
#pragma unroll
    for (int mt = 0; mt < 2; mt++)
#pragma unroll
        for (int nf = 0; nf < 4; nf++)
#pragma unroll
            for (int r = 0; r < 4; r++) acc[mt][nf][r] = 0.f;

    float4 aReg[4], wReg[4];
#pragma unroll
    for (int i = 0; i < 4; i++) {
        int row = lr + 16 * i;
        aReg[i] = *(const float4*)&Amat[(size_t)row * K + lc16 * 4];
        wReg[i] = *(const float4*)&Wmat[(size_t)(n0 + row) * K + lc16 * 4];
    }

    int st = 0;
    for (int k0 = 0; k0 < K; k0 += 32) {
#pragma unroll
        for (int i = 0; i < 4; i++) {
            int row = lr + 16 * i;
            unsigned off = row * 128 + (unsigned)((lc16 ^ (row & 7)) << 4);
            *(uint4*)(gsm[st] + off) = cvt4(aReg[i]);
            *(uint4*)(gsm[st] + 8192 + off) = cvt4(wReg[i]);
        }
        __syncthreads();

        if (k0 + 32 < K) {
#pragma unroll
            for (int i = 0; i < 4; i++) {
                int row = lr + 16 * i;
                aReg[i] = *(const float4*)&Amat[(size_t)row * K + k0 + 32 + lc16 * 4];
                wReg[i] = *(const float4*)&Wmat[(size_t)(n0 + row) * K + k0 + 32 + lc16 * 4];
            }
        }

        unsigned Ab = sbase + st * 16384;
        unsigned Wb = Ab + 8192;
#pragma unroll
        for (int ks = 0; ks < 4; ks++) {
            unsigned a0[4], a1[4], b0[4], b1[4];
            unsigned acol = ((unsigned)(ks * 2 + akh) ^ am) << 4;
            unsigned bcol = ((unsigned)(ks * 2 + bkh) ^ bm) << 4;
            ldsm4(a0, Ab + aRow0 + acol);
            ldsm4(a1, Ab + aRow1 + acol);
            ldsm4(b0, Wb + bRow0 + bcol);
            ldsm4(b1, Wb + bRow1 + bcol);
            mma_tf32(acc[0][0], a0, b0);
            mma_tf32(acc[0][1], a0, b0 + 2);
            mma_tf32(acc[1][0], a1, b0);
            mma_tf32(acc[1][1], a1, b0 + 2);
            mma_tf32(acc[0][2], a0, b1);
            mma_tf32(acc[0][3], a0, b1 + 2);
            mma_tf32(acc[1][2], a1, b1);
            mma_tf32(acc[1][3], a1, b1 + 2);
        }
        __syncthreads();
        st ^= 1;
    }

#pragma unroll
    for (int mt = 0; mt < 2; mt++) {
        int m0i = mb + mt * 16 + g;
        int m1i = m0i + 8;
#pragma unroll
        for (int nf = 0; nf < 4; nf++) {
            int n = n0 + nb + nf * 8 + 2 * tig;
            float badd0 = 0.f, badd1 = 0.f;
            if (bias)  { badd0 += bias[n];  badd1 += bias[n + 1]; }
            if (bias2) { badd0 += bias2[n]; badd1 += bias2[n + 1]; }
            float v00 = acc[mt][nf][0] + badd0, v01 = acc[mt][nf][1] + badd1;
            float v10 = acc[mt][nf][2] + badd0, v11 = acc[mt][nf][3] + badd1;
            if (accumulate) {
                v00 += Cmat[(size_t)m0i * N + n];  v01 += Cmat[(size_t)m0i * N + n + 1];
                v10 += Cmat[(size_t)m1i * N + n];  v11 += Cmat[(size_t)m1i * N + n + 1];
            }
            Cmat[(size_t)m0i * N + n] = v00;  Cmat[(size_t)m0i * N + n + 1] = v01;
            Cmat[(size_t)m1i * N + n] = v10;  Cmat[(size_t)m1i * N + n + 1] = v11;
        }
    }
}

// ---------------- score init ----------------
__global__ void score_init_kernel(const float* __restrict__ bva, float* __restrict__ score) {
    int i = blockIdx.x * blockDim.x + threadIdx.x;
    if (i < Bn * Sn) score[i] = bva[0];
}

// ---------------- fused attention score GEMM ----------------
// BM=128, BN=128, BK=32, 512 threads (16 warps: 4m x 4n, warp tile 32x32).
// 3-stage cp.async pipeline, single syncthreads per iter.
// grid: (A/128 = 8, BS/128 = 512), x fastest -> enc tile L2 reuse.
__global__ __launch_bounds__(512) void score_gemm_mma(
        const float* __restrict__ enc_tf, const float* __restrict__ wae_tf,
        const float* __restrict__ ba_e, const float* __restrict__ q,
        const float* __restrict__ va, float* __restrict__ score) {
    extern __shared__ char smem_raw[];
    unsigned sbase = (unsigned)__cvta_generic_to_shared(smem_raw);
    const unsigned STAGE = 32768;  // A 16KB + W 16KB
    float* qb  = (float*)(smem_raw + 3 * STAGE);
    float* vas = qb + 128;

    int tid = threadIdx.x;
    int w = tid >> 5, lane = tid & 31, g = lane >> 2, tig = lane & 3;
    int n0 = blockIdx.x * 128;
    int m0 = blockIdx.y * 128;
    int b = m0 >> 10;
    int mb = (w >> 2) * 32;
    int nb = (w & 3) * 32;

    if (tid < 128) {
        qb[tid]  = q[b * An + n0 + tid] + ba_e[n0 + tid];
        vas[tid] = va[n0 + tid];
    }

    int crow = tid >> 3;    // 0..63
    int ccol = tid & 7;
    const float* encp = enc_tf + (size_t)m0 * En;
    const float* waep = wae_tf + (size_t)n0 * En;

    int rA = mb + (lane & 15);
    int akh = (lane >> 4) & 1;
    unsigned aRow0 = rA * 128, aRow1 = (rA + 16) * 128;
    int am = rA & 7;
    int rB = nb + ((lane >> 1) & 8) + (lane & 7);
    int bkh = (lane >> 3) & 1;
    unsigned bRow0 = rB * 128, bRow1 = (rB + 16) * 128;
    int bm = rB & 7;

    float acc[2][4][4];
#pragma unroll
    for (int mt = 0; mt < 2; mt++)
#pragma unroll
        for (int nf = 0; nf < 4; nf++)
#pragma unroll
            for (int r = 0; r < 4; r++) acc[mt][nf][r] = 0.f;

#define PREFETCH(st, k0)                                                          \
    do {                                                                          \
        unsigned Ad = sbase + (st) * STAGE;                                       \
        unsigned Wd = Ad + 16384;                                                 \
        _Pragma("unroll")                                                         \
        for (int i = 0; i < 2; i++) {                                             \
            int row = crow + i * 64;                                              \
            cp_async16(Ad + row * 128 + ((ccol ^ (row & 7)) << 4),                \
                       encp + (size_t)row * En + (k0) + ccol * 4);                \
        }                                                                         \
        _Pragma("unroll")                                                         \
        for (int i = 0; i < 2; i++) {                                             \
            int row = crow + i * 64;                                              \
            cp_async16(Wd + row * 128 + ((ccol ^ (row & 7)) << 4),                \
                       waep + (size_t)row * En + (k0) + ccol * 4);                \
        }                                                                         \
        cp_commit();                                                              \
    } while (0)

    PREFETCH(0, 0);
    PREFETCH(1, 32);

    const int NT = En / 32;
    int st = 0;
    for (int it = 0; it < NT; it++) {
        if (it == NT - 1) asm volatile("cp.async.wait_group 0;");
        else              asm volatile("cp.async.wait_group 1;");
        __syncthreads();

        unsigned Ab = sbase + st * STAGE;
        unsigned Wb = Ab + 16384;
#pragma unroll
        for (int ks = 0; ks < 4; ks++) {
            unsigned a0[4], a1[4], b0[4], b1[4];
            unsigned acol = ((unsigned)(ks * 2 + akh) ^ am) << 4;
            unsigned bcol = ((unsigned)(ks * 2 + bkh) ^ bm) << 4;
            ldsm4(a0, Ab + aRow0 + acol);
            ldsm4(a1, Ab + aRow1 + acol);
            ldsm4(b0, Wb + bRow0 + bcol);
            ldsm4(b1, Wb + bRow1 + bcol);
            mma_tf32(acc[0][0], a0, b0);
            mma_tf32(acc[0][1], a0, b0 + 2);
            mma_tf32(acc[1][0], a1, b0);
            mma_tf32(acc[1][1], a1, b0 + 2);
            mma_tf32(acc[0][2], a0, b1);
            mma_tf32(acc[0][3], a0, b1 + 2);
            mma_tf32(acc[1][2], a1, b1);
            mma_tf32(acc[1][3], a1, b1 + 2);
        }

        int pf = it + 2;
        if (pf < NT) PREFETCH(pf % 3, pf * 32);
        st = (st + 1 == 3) ? 0 : st + 1;
    }
#undef PREFETCH

    // epilogue: tanh + va-weighted row reduction
#pragma unroll
    for (int mt = 0; mt < 2; mt++) {
        float sumlo = 0.f, sumhi = 0.f;
#pragma unroll
        for (int nf = 0; nf < 4; nf++) {
            int nl = nb + nf * 8 + 2 * tig;
            float q0 = qb[nl], q1 = qb[nl + 1];
            float v0 = vas[nl], v1 = vas[nl + 1];
            sumlo += v0 * tanhf(acc[mt][nf][0] + q0) + v1 * tanhf(acc[mt][nf][1] + q1);
            sumhi += v0 * tanhf(acc[mt][nf][2] + q0) + v1 * tanhf(acc[mt][nf][3] + q1);
        }
        sumlo += __shfl_xor_sync(0xffffffffu, sumlo, 1);
        sumlo += __shfl_xor_sync(0xffffffffu, sumlo, 2);
        sumhi += __shfl_xor_sync(0xffffffffu, sumhi, 1);
        sumhi += __shfl_xor_sync(0xffffffffu, sumhi, 2);
        if (tig == 0) {
            int r = m0 + mb + mt * 16 + g;
            atomicAdd(&score[r], sumlo);
            atomicAdd(&score[r + 8], sumhi);
        }
    }
}

// ---------------- softmax ----------------
__global__ void softmax_kernel(const float* __restrict__ score, float* __restrict__ attn) {
    __shared__ float sh[Sn];
    __shared__ float red[256];
    int b = blockIdx.x;
    int tid = threadIdx.x;

    float lmax = -3.4e38f;
    for (int s = tid; s < Sn; s += 256) {
        float v = score[b * Sn + s];
        sh[s] = v;
        lmax = fmaxf(lmax, v);
    }
    red[tid] = lmax;
    __syncthreads();
    for (int off = 128; off > 0; off >>= 1) {
        if (tid < off) red[tid] = fmaxf(red[tid], red[tid + off]);
        __syncthreads();
    }
    float m = red[0];
    __syncthreads();

    float lsum = 0.f;
    for (int s = tid; s < Sn; s += 256) {
        float e = expf(sh[s] - m);
        sh[s] = e;
        lsum += e;
    }
    red[tid] = lsum;
    __syncthreads();
    for (int off = 128; off > 0; off >>= 1) {
        if (tid < off) red[tid] += red[tid + off];
        __syncthreads();
    }
    float inv = 1.f / red[0];
    __syncthreads();

    for (int s = tid; s < Sn; s += 256) attn[b * Sn + s] = sh[s] * inv;
}

// ---------------- context = attn @ enc ----------------
__global__ void context_kernel(const float* __restrict__ enc,
                               const float* __restrict__ attn,
                               float* __restrict__ xbuf) {
    __shared__ float w[Sn];
    int b = blockIdx.x;
    int e = blockIdx.y * 256 + threadIdx.x;
    for (int s = threadIdx.x; s < Sn; s += 256) w[s] = attn[b * Sn + s];
    __syncthreads();
    const float* ep = enc + (size_t)b * Sn * En + e;
    float acc = 0.f;
#pragma unroll 8
    for (int s = 0; s < Sn; s++) acc += w[s] * ep[(size_t)s * En];
    xbuf[(size_t)b * (Dn + En) + Dn + e] = acc;
}

// ---------------- LSTM pointwise ----------------
__global__ void lstm_pointwise(const float* __restrict__ gates,
                               const float* __restrict__ cprev,
                               float* __restrict__ hout,
                               float* __restrict__ cout) {
    int idx = blockIdx.x * 256 + threadIdx.x;
    if (idx >= Bn * Hn) return;
    int b = idx >> 10;
    int h = idx & 1023;
    const float* g = gates + (size_t)b * 4 * Hn;
    float ig = 1.f / (1.f + expf(-g[h]));
    float fg = 1.f / (1.f + expf(-g[Hn + h]));
    float gg = tanhf(g[2 * Hn + h]);
    float og = 1.f / (1.f + expf(-g[3 * Hn + h]));
    float c = fg * cprev[idx] + ig * gg;
    hout[idx] = og * tanhf(c);
    cout[idx] = c;
}

// ---------------- launcher ----------------
extern "C" void kernel_launch(void* const* d_in, const int* in_sizes, int n_in,
                              void* d_out, int out_size) {
    const int*   input_step = (const int*)d_in[0];
    const float* h0    = (const float*)d_in[1];
    const float* c0    = (const float*)d_in[2];
    const float* enc   = (const float*)d_in[3];
    const float* emb   = (const float*)d_in[4];
    const float* Wa_h  = (const float*)d_in[5];
    const float* ba_h  = (const float*)d_in[6];
    const float* Wa_e  = (const float*)d_in[7];
    const float* ba_e  = (const float*)d_in[8];
    const float* va    = (const float*)d_in[9];
    const float* bva   = (const float*)d_in[10];
    const float* Wih0  = (const float*)d_in[11];
    const float* Whh0  = (const float*)d_in[12];
    const float* bih0  = (const float*)d_in[13];
    const float* bhh0  = (const float*)d_in[14];
    const float* Wih1  = (const float*)d_in[15];
    const float* Whh1  = (const float*)d_in[16];
    const float* bih1  = (const float*)d_in[17];
    const float* bhh1  = (const float*)d_in[18];
    const float* Wout  = (const float*)d_in[19];
    const float* bout  = (const float*)d_in[20];

    float* out = (float*)d_out;
    float* out_logits = out;
    float* out_h      = out_logits + Bn * Vn;
    float* out_c      = out_h + 2 * Bn * Hn;
    float* out_attn   = out_c + 2 * Bn * Hn;

    float* q_buf;     cudaGetSymbolAddress((void**)&q_buf, g_q);
    float* score_buf; cudaGetSymbolAddress((void**)&score_buf, g_score);
    float* x_buf;     cudaGetSymbolAddress((void**)&x_buf, g_x);
    float* gates_buf; cudaGetSymbolAddress((void**)&gates_buf, g_gates);
    float* enc_tf;    cudaGetSymbolAddress((void**)&enc_tf, g_enc_tf);
    float* wae_tf;    cudaGetSymbolAddress((void**)&wae_tf, g_wae_tf);

    const int score_smem = 3 * 32768 + 1024;  // 99328
    cudaFuncSetAttribute(score_gemm_mma, cudaFuncAttributeMaxDynamicSharedMemorySize,
                         score_smem);

    // 0. pre-round enc and Wa_e to tf32 (rna)
    tf32_convert<<<(Bn * Sn * En) / 1024, 256>>>(enc, enc_tf);
    tf32_convert<<<(An * En) / 1024, 256>>>(Wa_e, wae_tf);

    // 1. embedding gather
    embed_kernel<<<Bn, 256>>>(input_step, emb, x_buf);

    // 2. q = h0[1] @ Wa_h^T + ba_h
    gemm_nt_tc<<<An / 64, 128>>>(h0 + Bn * Hn, Wa_h, ba_h, nullptr, q_buf, Hn, An, 0);

    // 3. fused tf32 score GEMM
    score_init_kernel<<<(Bn * Sn + 255) / 256, 256>>>(bva, score_buf);
    {
        dim3 grid(An / 128, Bn * Sn / 128);
        score_gemm_mma<<<grid, 512, score_smem>>>(enc_tf, wae_tf, ba_e, q_buf, va, score_buf);
    }

    // 4. softmax
    softmax_kernel<<<Bn, 256>>>(score_buf, out_attn);

    // 5. context
    {
        dim3 grid(Bn, En / 256);
        context_kernel<<<grid, 256>>>(enc, out_attn, x_buf);
    }

    // 6. LSTM layer 0
    gemm_nt_tc<<<4 * Hn / 64, 128>>>(x_buf, Wih0, bih0, bhh0, gates_buf, Dn + En, 4 * Hn, 0);
    gemm_nt_tc<<<4 * Hn / 64, 128>>>(h0, Whh0, nullptr, nullptr, gates_buf, Hn, 4 * Hn, 1);
    lstm_pointwise<<<(Bn * Hn + 255) / 256, 256>>>(gates_buf, c0, out_h, out_c);

    // 7. LSTM layer 1
    gemm_nt_tc<<<4 * Hn / 64, 128>>>(out_h, Wih1, bih1, bhh1, gates_buf, Hn, 4 * Hn, 0);
    gemm_nt_tc<<<4 * Hn / 64, 128>>>(h0 + Bn * Hn, Whh1, nullptr, nullptr, gates_buf, Hn, 4 * Hn, 1);
    lstm_pointwise<<<(Bn * Hn + 255) / 256, 256>>>(gates_buf, c0 + Bn * Hn,
                                                   out_h + Bn * Hn, out_c + Bn * Hn);

    // 8. logits
    gemm_nt_tc<<<Vn / 64, 128>>>(out_h + Bn * Hn, Wout, bout, nullptr, out_logits, Hn, Vn, 0);
}